// round 9
// baseline (speedup 1.0000x reference)
#include <cuda_runtime.h>
#include <cuda_fp16.h>
#include <cstdint>

// ============================================================================
// MultiHeadGraphAttentionLayer — reduced form.
// softmax rows sum to 1, so out = hp = h @ Wcat : [16384,256] x [256,256].
// Prepass: tiny swizzled fp16 B images of Wcat^T only.
// GEMM: A staged as RAW fp32 via cp.async (triple-buffered, XOR-swizzled),
// A fragments built with LDS.64 + in-register fp16 pack (no h prepass);
// B verbatim cp.async image + ldmatrix. mma.sync.m16n8k16. sm_103 base ISA.
// ============================================================================

static constexpr int M_TOTAL = 16384;
static constexpr int N_OUT   = 256;
static constexpr int K_DIM   = 256;

static constexpr int CTA_M   = 128;
static constexpr int CTA_N   = 128;
static constexpr int THREADS = 256;

static constexpr int KSLAB   = 32;              // fp32 k-floats per slab
static constexpr int NSLICE  = K_DIM / KSLAB;   // 8

static constexpr int B_IMG_HALVES = CTA_N * K_DIM;          // 32768 (64 KB)
static constexpr int B_CHUNK_B    = 16384;                  // one k-group of 4 k-steps
static constexpr int A_SLAB_BYTES = CTA_M * KSLAB * 4;      // 16384 (fp32)
static constexpr int SMEM_BYTES   = B_IMG_HALVES * 2 + 3 * A_SLAB_BYTES; // 114688

// swizzled fp16 B images (128 KB) — static device scratch (no allocation)
__device__ __align__(16) __half g_bt[2 * B_IMG_HALVES];

__device__ __forceinline__ uint32_t smem_u32(const void* p) {
    uint32_t a;
    asm("{ .reg .u64 t; cvta.to.shared.u64 t, %1; cvt.u32.u64 %0, t; }"
        : "=r"(a) : "l"(p));
    return a;
}

__device__ __forceinline__ void ldm_x4(uint32_t* r, uint32_t addr) {
    asm volatile("ldmatrix.sync.aligned.m8n8.x4.shared.b16 {%0,%1,%2,%3}, [%4];"
                 : "=r"(r[0]), "=r"(r[1]), "=r"(r[2]), "=r"(r[3])
                 : "r"(addr));
}

__device__ __forceinline__ void mma16816(float* c, const uint32_t* a,
                                         const uint32_t* b) {
    asm volatile(
        "mma.sync.aligned.m16n8k16.row.col.f32.f16.f16.f32 "
        "{%0,%1,%2,%3}, {%4,%5,%6,%7}, {%8,%9}, {%0,%1,%2,%3};"
        : "+f"(c[0]), "+f"(c[1]), "+f"(c[2]), "+f"(c[3])
        : "r"(a[0]), "r"(a[1]), "r"(a[2]), "r"(a[3]), "r"(b[0]), "r"(b[1]));
}

__device__ __forceinline__ uint32_t pack_h2(float2 v) {
    __half2 h = __floats2half2_rn(v.x, v.y);
    return *reinterpret_cast<uint32_t*>(&h);
}

#define CP_ASYNC_16(smem_addr, gptr)                                           \
    asm volatile("cp.async.cg.shared.global [%0], [%1], 16;"                   \
                 :: "r"(smem_addr), "l"(gptr))
#define CP_ASYNC_COMMIT() asm volatile("cp.async.commit_group;")
#define CP_ASYNC_WAIT(n)  asm volatile("cp.async.wait_group %0;" :: "n"(n))

// B image byte offset for local row c (0..127), col f (0..255)
__device__ __forceinline__ uint32_t b_img_off(int c, int f) {
    uint32_t off = (uint32_t)(((c >> 3) + (f >> 6) * 16) * 1024
                              + (c & 7) * 128 + (f & 63) * 2);
    return off ^ ((off >> 3) & 0x70);
}

// ---------------- prepass: B images only ----------------
__global__ __launch_bounds__(512)
void prep_b_kernel(const float* __restrict__ W) {
    int u = blockIdx.x * blockDim.x + threadIdx.x;   // 0..65535
    if (u < 2 * B_IMG_HALVES) {
        int img = u >> 15;
        int rem = u & 32767;
        int f   = rem >> 7;          // 0..255
        int c   = rem & 127;         // local col (consecutive -> coalesced d)
        int n   = img * 128 + c;
        int hh  = n >> 6;
        int d   = n & 63;
        float w = W[hh * 16384 + f * 64 + d];
        g_bt[img * B_IMG_HALVES + (b_img_off(c, f) >> 1)] = __float2half_rn(w);
    }
}

// ---------------- GEMM ----------------
__global__ __launch_bounds__(THREADS, 2)
void gat_gemm_kernel(const float* __restrict__ hin,
                     float* __restrict__ out) {
    extern __shared__ char smem[];
    char* Bs = smem;                          // 64 KB swizzled fp16 image
    char* As = smem + B_IMG_HALVES * 2;       // 3 x 16 KB fp32 slabs

    const int tid  = threadIdx.x;
    const int wid  = tid >> 5;
    const int lane = tid & 31;

    const int bm   = blockIdx.x >> 1;
    const int img  = blockIdx.x & 1;
    const int bn   = img * CTA_N;
    const long arow0 = (long)bm * CTA_M;

    const float*  aGlob = hin + arow0 * K_DIM;
    const __half* bGlob = g_bt + img * B_IMG_HALVES;
    const uint32_t BsU = smem_u32(Bs);
    const uint32_t AsU = smem_u32(As);

    // A slab: 128 rows x 32 fp32 (128 B/row), XOR swizzle on 16B chunks
    #define ISSUE_A(s, buf) do {                                               \
        const float* _src = aGlob + (s) * KSLAB;                               \
        _Pragma("unroll")                                                      \
        for (int i = 0; i < 4; i++) {                                          \
            int c = tid + i * THREADS;                                         \
            int r = c >> 3, q = c & 7;                                         \
            uint32_t dst = AsU + (uint32_t)((buf) * A_SLAB_BYTES + r * 128     \
                                            + ((q * 16) ^ ((r & 7) << 4)));  \
            CP_ASYNC_16(dst, _src + r * K_DIM + q * 4);                        \
        }                                                                      \
    } while (0)

    // head: G0 = {B image (verbatim), A slab 0}, G1 = {A slab 1}
    {
        #pragma unroll
        for (int i = 0; i < 16; i++) {
            int c = tid + i * THREADS;
            CP_ASYNC_16(BsU + (uint32_t)(c * 16), bGlob + c * 8);
        }
    }
    ISSUE_A(0, 0); CP_ASYNC_COMMIT();
    ISSUE_A(1, 1); CP_ASYNC_COMMIT();

    // ---- warp tiling: 8 warps = 4(m) x 2(n); warp tile 32(m) x 64(n) ----
    const int wm = wid & 3;
    const int wn = wid >> 2;

    float acc[2][8][4];
    #pragma unroll
    for (int mt = 0; mt < 2; mt++)
        #pragma unroll
        for (int nt = 0; nt < 8; nt++)
            #pragma unroll
            for (int q = 0; q < 4; q++) acc[mt][nt][q] = 0.f;

    // A fragment addressing (fp32 slab): thread row fr = lane>>2, col fc = (lane&3)*2
    // a0=(r,fc) a1=(r+8,fc) a2=(r,fc+8) a3=(r+8,fc+8); r = wm*32 + mt*16 + fr
    // byte addr = rowbase + ((qc*16) ^ (fr<<4)) + (fc&3)*4, qc = c>>2
    const int fr = lane >> 2;
    const int fc = (lane & 3) * 2;
    const uint32_t aX  = (uint32_t)(fr << 4);
    const uint32_t aW  = (uint32_t)((fc & 3) * 4);
    uint32_t aRowB[4];                     // mt0: r, r+8 ; mt1: r+16, r+24
    #pragma unroll
    for (int j = 0; j < 4; j++)
        aRowB[j] = (uint32_t)((wm * 32 + fr + j * 8) * 128);

    // B lane addressing (verified)
    const int rB    = wn * 64 + ((lane >> 4) << 3) + (lane & 7);
    const uint32_t bXor = (uint32_t)((rB & 7) << 4);
    const int bkl   = ((lane >> 3) & 1) * 8;
    uint32_t bBase[4];
    #pragma unroll
    for (int nt2 = 0; nt2 < 4; nt2++) {
        int r = rB + nt2 * 16;
        bBase[nt2] = BsU + (uint32_t)((r >> 3) * 1024 + (r & 7) * 128);
    }

    #pragma unroll
    for (int s = 0; s < NSLICE; s++) {
        if (s < NSLICE - 1) { CP_ASYNC_WAIT(1); } else { CP_ASYNC_WAIT(0); }
        __syncthreads();
        if (s + 2 < NSLICE) {            // buffer (s+2)%3 == (s-1)%3 is free now
            ISSUE_A(s + 2, (s + 2) % 3);
            CP_ASYNC_COMMIT();
        }

        const char* aStage = As + (s % 3) * A_SLAB_BYTES;
        #pragma unroll
        for (int ks = 0; ks < 2; ks++) {            // 2 k-steps per 32-fp32 slab
            const int kg = s * 2 + ks;
            // column offsets within slab for this k-step
            const int c0 = fc + ks * 16;            // 0..22
            const uint32_t off0 = (uint32_t)((((c0 >> 2) * 16) ^ aX) + aW);
            const uint32_t off8 = (uint32_t)(((((c0 + 8) >> 2) * 16) ^ aX) + aW);

            uint32_t a[2][4];
            #pragma unroll
            for (int mt = 0; mt < 2; mt++) {
                float2 v0 = *reinterpret_cast<const float2*>(aStage + aRowB[mt*2]   + off0);
                float2 v1 = *reinterpret_cast<const float2*>(aStage + aRowB[mt*2+1] + off0);
                float2 v2 = *reinterpret_cast<const float2*>(aStage + aRowB[mt*2]   + off8);
                float2 v3 = *reinterpret_cast<const float2*>(aStage + aRowB[mt*2+1] + off8);
                a[mt][0] = pack_h2(v0);
                a[mt][1] = pack_h2(v1);
                a[mt][2] = pack_h2(v2);
                a[mt][3] = pack_h2(v3);
            }

            uint32_t b[4][4];
            const uint32_t kOff = (uint32_t)((kg >> 2) * B_CHUNK_B)
                                + (uint32_t)((((kg & 3) * 16 + bkl) * 2) ^ bXor);
            #pragma unroll
            for (int nt2 = 0; nt2 < 4; nt2++)
                ldm_x4(b[nt2], bBase[nt2] + kOff);

            #pragma unroll
            for (int mt = 0; mt < 2; mt++)
                #pragma unroll
                for (int nt = 0; nt < 8; nt++)
                    mma16816(acc[mt][nt], a[mt], &b[nt >> 1][(nt & 1) * 2]);
        }
    }
    #undef ISSUE_A

    // ---- epilogue: direct fp32 stores ----
    const int g  = lane >> 2;
    const int tg = lane & 3;
    #pragma unroll
    for (int mt = 0; mt < 2; mt++) {
        #pragma unroll
        for (int nt = 0; nt < 8; nt++) {
            long row = arow0 + wm * 32 + mt * 16 + g;
            int  col = bn + wn * 64 + nt * 8 + tg * 2;
            float2 v0 = make_float2(acc[mt][nt][0], acc[mt][nt][1]);
            float2 v1 = make_float2(acc[mt][nt][2], acc[mt][nt][3]);
            *reinterpret_cast<float2*>(out + row * N_OUT + col)       = v0;
            *reinterpret_cast<float2*>(out + (row + 8) * N_OUT + col) = v1;
        }
    }
}

extern "C" void kernel_launch(void* const* d_in, const int* in_sizes, int n_in,
                              void* d_out, int out_size) {
    const float* h = (const float*)d_in[0];
    const float* W = (const float*)d_in[1];
    if (n_in >= 2 && in_sizes[0] < in_sizes[1]) {
        const float* t = h; h = W; W = t;
    }
    prep_b_kernel<<<(2 * B_IMG_HALVES + 511) / 512, 512>>>(W);

    cudaFuncSetAttribute(gat_gemm_kernel,
                         cudaFuncAttributeMaxDynamicSharedMemorySize, SMEM_BYTES);
    const int grid = (M_TOTAL / CTA_M) * (N_OUT / CTA_N);  // 256
    gat_gemm_kernel<<<grid, THREADS, SMEM_BYTES>>>(h, (float*)d_out);
}